// round 11
// baseline (speedup 1.0000x reference)
#include <cuda_runtime.h>
#include <cstdint>

#define BATCH 8
#define SEQ   2048
#define EMB   1024
#define HEAD  64
#define NTOK  (BATCH*SEQ)   // 16384
#define LOG2E 1.4426950408889634f
#define QSCALE (0.03125f * LOG2E)   // C^-0.5 * log2(e)

// ---------------------------------------------------------------------------
// PTX helpers (family-portable only)
// ---------------------------------------------------------------------------
__device__ __forceinline__ float tf32r(float x) {
    float y; asm("cvt.rna.tf32.f32 %0, %1;" : "=f"(y) : "f"(x)); return y;
}
__device__ __forceinline__ void mma_tf32(float* d, const uint32_t* a, const uint32_t* b) {
    asm volatile(
        "mma.sync.aligned.m16n8k8.row.col.f32.tf32.tf32.f32 "
        "{%0,%1,%2,%3}, {%4,%5,%6,%7}, {%8,%9}, {%0,%1,%2,%3};"
        : "+f"(d[0]), "+f"(d[1]), "+f"(d[2]), "+f"(d[3])
        : "r"(a[0]), "r"(a[1]), "r"(a[2]), "r"(a[3]), "r"(b[0]), "r"(b[1]));
}
__device__ __forceinline__ uint32_t s32(const void* p) {
    return (uint32_t)__cvta_generic_to_shared(p);
}
#define CP_ASYNC16(dst, src) \
    asm volatile("cp.async.cg.shared.global [%0], [%1], 16;" :: "r"(dst), "l"(src))
#define CP_COMMIT() asm volatile("cp.async.commit_group;" ::: "memory")
#define CP_WAIT0()  asm volatile("cp.async.wait_group 0;" ::: "memory")

// ---------------------------------------------------------------------------
// device scratch (Q pre-scaled; Q,K,V tf32-rounded at production)
// ---------------------------------------------------------------------------
__device__ float g_Q[NTOK*HEAD];
__device__ float g_K[NTOK*HEAD];
__device__ float g_V[NTOK*HEAD];

// ---------------------------------------------------------------------------
// Kernel 1: QKV projection, mma.sync tf32, N-split for 2 CTAs/SM.
// grid (128, 2): x = M-tile of 128 tokens, y = 32-col half of all 3 matrices.
// 256 threads = 8 warps (4m x 2n); warp tile 32m x 16n per matrix.
// smem (static): Xs[128][68] | Ws[3][64][36] = 15616 floats = 62464 B
// ---------------------------------------------------------------------------
__global__ __launch_bounds__(256, 2) void qkv_mma(
    const float* __restrict__ X,
    const float* __restrict__ Wq,
    const float* __restrict__ Wk,
    const float* __restrict__ Wv)
{
    __shared__ float Xs[128*68];      // [m][k] pitch 68
    __shared__ float Ws[3][64][36];   // [w][k][n-half] pitch 36

    const int tid  = threadIdx.x;
    const int wid  = tid >> 5;
    const int lane = tid & 31;
    const int mw   = wid >> 1;        // 0..3 (32 m-rows)
    const int nw   = wid & 1;         // 0..1 (16 n-cols)
    const int m0   = blockIdx.x * 128;
    const int n0   = blockIdx.y * 32;
    const int r = lane >> 2;
    const int c = lane & 3;

    const float* Wsrc[3] = { Wq, Wk, Wv };

    float acc[3][2][2][4];
    #pragma unroll
    for (int w = 0; w < 3; w++)
        #pragma unroll
        for (int mf = 0; mf < 2; mf++)
            #pragma unroll
            for (int nf = 0; nf < 2; nf++)
                #pragma unroll
                for (int e = 0; e < 4; e++) acc[w][mf][nf][e] = 0.f;

    for (int kt = 0; kt < 16; kt++) {          // 16 K-tiles of 64
        __syncthreads();
        // X tile 128x64 natural (2048 f4, 8/thread), tf32-rounded
        #pragma unroll
        for (int it = 0; it < 8; it++) {
            int f = tid + it * 256, cc = f & 15, rr = f >> 4;
            float4 v = *(const float4*)&X[(size_t)(m0 + rr) * EMB + kt*64 + 4*cc];
            v.x = tf32r(v.x); v.y = tf32r(v.y); v.z = tf32r(v.z); v.w = tf32r(v.w);
            *(float4*)&Xs[rr*68 + 4*cc] = v;
        }
        // W half-tiles 3 x 64x32 (1536 f4, 6/thread)
        #pragma unroll
        for (int it = 0; it < 6; it++) {
            int f = tid + it * 256, w = f >> 9, rem = f & 511;
            int cc = rem & 7, rr = rem >> 3;
            float4 v = *(const float4*)&Wsrc[w][(size_t)(kt*64 + rr) * HEAD + n0 + 4*cc];
            v.x = tf32r(v.x); v.y = tf32r(v.y); v.z = tf32r(v.z); v.w = tf32r(v.w);
            *(float4*)&Ws[w][rr][4*cc] = v;
        }
        __syncthreads();

        #pragma unroll
        for (int ks = 0; ks < 8; ks++) {
            const int k = ks * 8;
            uint32_t a[2][4];
            #pragma unroll
            for (int mf = 0; mf < 2; mf++) {
                const int m = mw*32 + mf*16;
                a[mf][0] = __float_as_uint(Xs[(m + r    )*68 + k + c    ]);
                a[mf][1] = __float_as_uint(Xs[(m + r + 8)*68 + k + c    ]);
                a[mf][2] = __float_as_uint(Xs[(m + r    )*68 + k + c + 4]);
                a[mf][3] = __float_as_uint(Xs[(m + r + 8)*68 + k + c + 4]);
            }
            #pragma unroll
            for (int w = 0; w < 3; w++) {
                uint32_t b[2][2];
                #pragma unroll
                for (int nf = 0; nf < 2; nf++) {
                    const int n = nw*16 + nf*8;
                    b[nf][0] = __float_as_uint(Ws[w][k + c    ][n + r]);
                    b[nf][1] = __float_as_uint(Ws[w][k + c + 4][n + r]);
                }
                #pragma unroll
                for (int mf = 0; mf < 2; mf++)
                    #pragma unroll
                    for (int nf = 0; nf < 2; nf++)
                        mma_tf32(acc[w][mf][nf], a[mf], b[nf]);
            }
        }
    }

    // epilogue: Q pre-scaled; all tf32-rounded for the attention kernel
    #pragma unroll
    for (int w = 0; w < 3; w++) {
        float* Out = (w == 0) ? g_Q : (w == 1) ? g_K : g_V;
        const float sc = (w == 0) ? QSCALE : 1.f;
        #pragma unroll
        for (int mf = 0; mf < 2; mf++) {
            const int mrow = m0 + mw*32 + mf*16 + r;
            #pragma unroll
            for (int nf = 0; nf < 2; nf++) {
                const int n = n0 + nw*16 + nf*8 + 2*c;
                *(float2*)&Out[(size_t)mrow * HEAD + n] =
                    make_float2(tf32r(acc[w][mf][nf][0] * sc),
                                tf32r(acc[w][mf][nf][1] * sc));
                *(float2*)&Out[(size_t)(mrow + 8) * HEAD + n] =
                    make_float2(tf32r(acc[w][mf][nf][2] * sc),
                                tf32r(acc[w][mf][nf][3] * sc));
            }
        }
    }
}

// ---------------------------------------------------------------------------
// Balanced bid -> (qb, batch) decode.  Co-resident bids k and k+148 map to
// complementary q-blocks {q, 31-q} (per-SM tile total = 17 for every pair);
// the 40 partner-less bids (108..147) get qb 13..18 (<= 10 tiles).
// Every (qb, b) in [0,32) x [0,8) appears exactly once across 256 bids.
// ---------------------------------------------------------------------------
__device__ __forceinline__ void decode_bid(int bid, int& qb, int& b) {
    if (bid < 104)      { qb = bid >> 3;              b = bid & 7;   }  // 0..12
    else if (bid < 108) { qb = 13;                    b = bid - 104; }  // b 0..3
    else if (bid < 148) {
        int i = bid - 108;                 // 0..39 singles
        if (i < 4)      { qb = 13;         b = 4 + i; }
        else if (i < 8) { qb = 18;         b = i;     }                 // b 4..7
        else            { int j = i - 8;   qb = 14 + (j >> 3); b = j & 7; }
    }
    else if (bid < 252) { int i = bid - 148; qb = 31 - (i >> 3); b = i & 7; } // 31..19
    else                { qb = 18;                    b = bid - 252; }  // b 0..3
}

// ---------------------------------------------------------------------------
// Kernel 2: flash attention, mma.sync tf32.  One q-block of 64 per CTA,
// kv-tile 128, grid 256 flat (balanced decode), 256 threads = 8 warps
// (4m x 2n), 2 CTAs/SM.
// smem (floats): Qs 64x68 | Ks 128x68 (alias Ps 64x132) | Vs 128x68 | red 256
// = 4352 + 8704 + 8704 + 256 = 22016 floats = 88064 B  (2 x 88KB <= 227KB)
// ---------------------------------------------------------------------------
#define ATTN_SMEM_BYTES (22016 * 4)

__global__ __launch_bounds__(256, 2) void attn_mma(float* __restrict__ out)
{
    extern __shared__ float sm[];
    float* Qs = sm;                  // pitch 68
    float* Ks = sm + 4352;           // pitch 68, 128 rows
    float* Ps = Ks;                  // pitch 132, 64 rows (alias, 8448 <= 8704)
    float* Vs = sm + 13056;          // pitch 68, 128 rows
    float* redmax = sm + 21760;      // [2][64]
    float* redsum = redmax + 128;    // [2][64]

    const int tid  = threadIdx.x;
    const int wid  = tid >> 5;
    const int lane = tid & 31;
    const int mw   = wid >> 1;        // 0..3 (16 q-rows)
    const int nw   = wid & 1;         // 0..1 (64 keys / 32 head-cols)
    const int r    = lane >> 2;
    const int c    = lane & 3;

    int qb, b;
    decode_bid((int)blockIdx.x, qb, b);
    const int q0 = qb * 64;
    const int ntiles = q0 / 128 + 1;

    const float* Qg = g_Q + (size_t)b * SEQ * HEAD;
    const float* Kg = g_K + (size_t)b * SEQ * HEAD;
    const float* Vg = g_V + (size_t)b * SEQ * HEAD;

    const int rowbase = mw*16 + r;

    // prologue: stage Q (pre-scaled + tf32 at producer) + K(0) + V(0)
    #pragma unroll
    for (int it = 0; it < 4; it++) {
        int f = tid + it * 256, cc = f & 15, rr = f >> 4;
        CP_ASYNC16(s32(&Qs[rr*68 + 4*cc]),
                   &Qg[(size_t)(q0 + rr) * HEAD + 4*cc]);
    }
    #pragma unroll
    for (int it = 0; it < 8; it++) {
        int f = tid + it * 256, cc = f & 15, rr = f >> 4;
        CP_ASYNC16(s32(&Ks[rr*68 + 4*cc]), &Kg[(size_t)rr * HEAD + 4*cc]);
        CP_ASYNC16(s32(&Vs[rr*68 + 4*cc]), &Vg[(size_t)rr * HEAD + 4*cc]);
    }
    CP_COMMIT();

    float m_st[2] = { -1e30f, -1e30f };
    float l_st[2] = { 0.f, 0.f };
    float o[4][4];
    #pragma unroll
    for (int nf = 0; nf < 4; nf++)
        #pragma unroll
        for (int e = 0; e < 4; e++) o[nf][e] = 0.f;

    for (int kt = 0; kt < ntiles; kt++) {
        const int k0 = kt * 128;
        CP_WAIT0();
        __syncthreads();   // K(kt), V(kt) (and Q) visible CTA-wide

        // ----- S = Q K^T : warp tile 16q x 64keys -----
        float s[8][4];
        #pragma unroll
        for (int nf = 0; nf < 8; nf++)
            #pragma unroll
            for (int e = 0; e < 4; e++) s[nf][e] = 0.f;

        #pragma unroll
        for (int ks = 0; ks < 8; ks++) {
            const int k = ks * 8;
            uint32_t a[4];
            a[0] = __float_as_uint(Qs[(mw*16 + r    )*68 + k + c    ]);
            a[1] = __float_as_uint(Qs[(mw*16 + r + 8)*68 + k + c    ]);
            a[2] = __float_as_uint(Qs[(mw*16 + r    )*68 + k + c + 4]);
            a[3] = __float_as_uint(Qs[(mw*16 + r + 8)*68 + k + c + 4]);
            #pragma unroll
            for (int nf = 0; nf < 8; nf++) {
                const int n = nw*64 + nf*8;
                uint32_t bb[2];
                bb[0] = __float_as_uint(Ks[(n + r)*68 + k + c    ]);
                bb[1] = __float_as_uint(Ks[(n + r)*68 + k + c + 4]);
                mma_tf32(s[nf], a, bb);
            }
        }

        // ----- causal mask -----
        const int row0 = q0 + mw*16 + r;
        const int row1 = row0 + 8;
        if (k0 + 127 > q0) {
            #pragma unroll
            for (int nf = 0; nf < 8; nf++) {
                const int col = k0 + nw*64 + nf*8 + 2*c;
                if (col     > row0) s[nf][0] = -1e30f;
                if (col + 1 > row0) s[nf][1] = -1e30f;
                if (col     > row1) s[nf][2] = -1e30f;
                if (col + 1 > row1) s[nf][3] = -1e30f;
            }
        }

        // ----- row max: intra-warp over c, 2-way cross-warp via smem -----
        float pm0 = s[0][0], pm1 = s[0][2];
        #pragma unroll
        for (int nf = 0; nf < 8; nf++) {
            pm0 = fmaxf(pm0, fmaxf(s[nf][0], s[nf][1]));
            pm1 = fmaxf(pm1, fmaxf(s[nf][2], s[nf][3]));
        }
        #pragma unroll
        for (int off = 1; off <= 2; off <<= 1) {
            pm0 = fmaxf(pm0, __shfl_xor_sync(0xffffffffu, pm0, off));
            pm1 = fmaxf(pm1, __shfl_xor_sync(0xffffffffu, pm1, off));
        }
        if (c == 0) {
            redmax[nw*64 + rowbase    ] = pm0;
            redmax[nw*64 + rowbase + 8] = pm1;
        }
        __syncthreads();   // (A) QK reads of Ks complete CTA-wide

        float mn0 = fmaxf(m_st[0], fmaxf(redmax[rowbase    ], redmax[64 + rowbase    ]));
        float mn1 = fmaxf(m_st[1], fmaxf(redmax[rowbase + 8], redmax[64 + rowbase + 8]));
        float corr0 = exp2f(m_st[0] - mn0);
        float corr1 = exp2f(m_st[1] - mn1);
        m_st[0] = mn0; m_st[1] = mn1;

        // p = exp2(s - mn); write P (tf32) into Ps (alias Ks — safe after A)
        float rs0 = 0.f, rs1 = 0.f;
        #pragma unroll
        for (int nf = 0; nf < 8; nf++) {
            float p0 = exp2f(s[nf][0] - mn0);
            float p1 = exp2f(s[nf][1] - mn0);
            float p2 = exp2f(s[nf][2] - mn1);
            float p3 = exp2f(s[nf][3] - mn1);
            rs0 += p0 + p1;
            rs1 += p2 + p3;
            const int col = nw*64 + nf*8 + 2*c;
            *(float2*)&Ps[(rowbase    )*132 + col] =
                make_float2(tf32r(p0), tf32r(p1));
            *(float2*)&Ps[(rowbase + 8)*132 + col] =
                make_float2(tf32r(p2), tf32r(p3));
        }
        #pragma unroll
        for (int off = 1; off <= 2; off <<= 1) {
            rs0 += __shfl_xor_sync(0xffffffffu, rs0, off);
            rs1 += __shfl_xor_sync(0xffffffffu, rs1, off);
        }
        if (c == 0) {
            redsum[nw*64 + rowbase    ] = rs0;
            redsum[nw*64 + rowbase + 8] = rs1;
        }
        __syncthreads();   // (B) P + redsum visible

        l_st[0] = l_st[0] * corr0 + redsum[rowbase    ] + redsum[64 + rowbase    ];
        l_st[1] = l_st[1] * corr1 + redsum[rowbase + 8] + redsum[64 + rowbase + 8];

        #pragma unroll
        for (int nf = 0; nf < 4; nf++) {
            o[nf][0] *= corr0; o[nf][1] *= corr0;
            o[nf][2] *= corr1; o[nf][3] *= corr1;
        }

        // ----- O += P V : warp tile 16q x 32head, 16 k-steps -----
        #pragma unroll
        for (int ks = 0; ks < 16; ks++) {
            const int k = ks * 8;
            uint32_t a[4];
            a[0] = __float_as_uint(Ps[(mw*16 + r    )*132 + k + c    ]);
            a[1] = __float_as_uint(Ps[(mw*16 + r + 8)*132 + k + c    ]);
            a[2] = __float_as_uint(Ps[(mw*16 + r    )*132 + k + c + 4]);
            a[3] = __float_as_uint(Ps[(mw*16 + r + 8)*132 + k + c + 4]);
            #pragma unroll
            for (int nf = 0; nf < 4; nf++) {
                const int n = nw*32 + nf*8;
                uint32_t bb[2];
                bb[0] = __float_as_uint(Vs[(k + c    )*68 + n + r]);
                bb[1] = __float_as_uint(Vs[(k + c + 4)*68 + n + r]);
                mma_tf32(o[nf], a, bb);
            }
        }

        // stage next tile (PV done with Vs; Ps/Ks reads done)
        if (kt + 1 < ntiles) {
            __syncthreads();
            const int kn = (kt + 1) * 128;
            #pragma unroll
            for (int it = 0; it < 8; it++) {
                int f = tid + it * 256, cc = f & 15, rr = f >> 4;
                CP_ASYNC16(s32(&Ks[rr*68 + 4*cc]),
                           &Kg[(size_t)(kn + rr) * HEAD + 4*cc]);
                CP_ASYNC16(s32(&Vs[rr*68 + 4*cc]),
                           &Vg[(size_t)(kn + rr) * HEAD + 4*cc]);
            }
            CP_COMMIT();
        }
    }

    // epilogue: normalize, store
    const int row0 = q0 + mw*16 + r;
    const float inv0 = 1.f / l_st[0];
    const float inv1 = 1.f / l_st[1];
    #pragma unroll
    for (int nf = 0; nf < 4; nf++) {
        const int n = nw*32 + nf*8 + 2*c;
        *(float2*)&out[((size_t)b * SEQ + row0) * HEAD + n] =
            make_float2(o[nf][0] * inv0, o[nf][1] * inv0);
        *(float2*)&out[((size_t)b * SEQ + row0 + 8) * HEAD + n] =
            make_float2(o[nf][2] * inv1, o[nf][3] * inv1);
    }
}

// ---------------------------------------------------------------------------
extern "C" void kernel_launch(void* const* d_in, const int* in_sizes, int n_in,
                              void* d_out, int out_size)
{
    const float* X  = (const float*)d_in[0];
    const float* Wq = (const float*)d_in[1];
    const float* Wk = (const float*)d_in[2];
    const float* Wv = (const float*)d_in[3];
    float* out = (float*)d_out;

    cudaFuncSetAttribute(attn_mma,
                         cudaFuncAttributeMaxDynamicSharedMemorySize, ATTN_SMEM_BYTES);

    dim3 g1(128, 2);
    qkv_mma<<<g1, 256>>>(X, Wq, Wk, Wv);

    attn_mma<<<256, 256, ATTN_SMEM_BYTES>>>(out);
}

// round 12
// speedup vs baseline: 1.1238x; 1.1238x over previous
#include <cuda_runtime.h>
#include <cstdint>

#define BATCH 8
#define SEQ   2048
#define EMB   1024
#define HEAD  64
#define NTOK  (BATCH*SEQ)   // 16384
#define LOG2E 1.4426950408889634f
#define QSCALE (0.03125f * LOG2E)   // C^-0.5 * log2(e)

// ---------------------------------------------------------------------------
// PTX helpers (family-portable only)
// ---------------------------------------------------------------------------
__device__ __forceinline__ float tf32r(float x) {
    float y; asm("cvt.rna.tf32.f32 %0, %1;" : "=f"(y) : "f"(x)); return y;
}
__device__ __forceinline__ void mma_tf32(float* d, const uint32_t* a, const uint32_t* b) {
    asm volatile(
        "mma.sync.aligned.m16n8k8.row.col.f32.tf32.tf32.f32 "
        "{%0,%1,%2,%3}, {%4,%5,%6,%7}, {%8,%9}, {%0,%1,%2,%3};"
        : "+f"(d[0]), "+f"(d[1]), "+f"(d[2]), "+f"(d[3])
        : "r"(a[0]), "r"(a[1]), "r"(a[2]), "r"(a[3]), "r"(b[0]), "r"(b[1]));
}
__device__ __forceinline__ uint32_t s32(const void* p) {
    return (uint32_t)__cvta_generic_to_shared(p);
}
#define CP_ASYNC16(dst, src) \
    asm volatile("cp.async.cg.shared.global [%0], [%1], 16;" :: "r"(dst), "l"(src))
#define CP_COMMIT() asm volatile("cp.async.commit_group;" ::: "memory")
#define CP_WAIT0()  asm volatile("cp.async.wait_group 0;" ::: "memory")

// ---------------------------------------------------------------------------
// device scratch (Q pre-scaled; Q,K,V tf32-rounded at production)
// ---------------------------------------------------------------------------
__device__ float g_Q[NTOK*HEAD];
__device__ float g_K[NTOK*HEAD];
__device__ float g_V[NTOK*HEAD];

// ---------------------------------------------------------------------------
// Kernel 1: QKV projection (R8 version — best measured, 60.0us).
// M-tile 128, K-tile 64, grid 128, 256 threads = 8 warps (4m x 2n).
// X staged NATURAL row-major; tf32 rounding at staging.
// smem (dynamic): Xs[128][68] | Ws[3][64][68] = 21760 floats = 87040 B
// ---------------------------------------------------------------------------
#define QKV_SMEM_BYTES (21760 * 4)

__global__ __launch_bounds__(256, 1) void qkv_mma(
    const float* __restrict__ X,
    const float* __restrict__ Wq,
    const float* __restrict__ Wk,
    const float* __restrict__ Wv)
{
    extern __shared__ float qsm[];
    float* Xs = qsm;            // [m][k], pitch 68
    float* Ws = qsm + 8704;     // [w][k][n], pitch 68, 64 k-rows per w

    const int tid  = threadIdx.x;
    const int wid  = tid >> 5;
    const int lane = tid & 31;
    const int mw   = wid >> 1;
    const int nw   = wid & 1;
    const int m0   = blockIdx.x * 128;
    const int r = lane >> 2;
    const int c = lane & 3;

    const float* Wsrc[3] = { Wq, Wk, Wv };

    float acc[3][2][4][4];
    #pragma unroll
    for (int w = 0; w < 3; w++)
        #pragma unroll
        for (int mf = 0; mf < 2; mf++)
            #pragma unroll
            for (int nf = 0; nf < 4; nf++)
                #pragma unroll
                for (int e = 0; e < 4; e++) acc[w][mf][nf][e] = 0.f;

    for (int kt = 0; kt < 16; kt++) {
        __syncthreads();
        #pragma unroll
        for (int it = 0; it < 8; it++) {
            int f = tid + it * 256, cc = f & 15, rr = f >> 4;
            float4 v = *(const float4*)&X[(size_t)(m0 + rr) * EMB + kt*64 + 4*cc];
            v.x = tf32r(v.x); v.y = tf32r(v.y); v.z = tf32r(v.z); v.w = tf32r(v.w);
            *(float4*)&Xs[rr*68 + 4*cc] = v;
        }
        #pragma unroll
        for (int it = 0; it < 12; it++) {
            int f = tid + it * 256, w = f >> 10, rem = f & 1023;
            int cc = rem & 15, rr = rem >> 4;
            float4 v = *(const float4*)&Wsrc[w][(size_t)(kt*64 + rr) * HEAD + 4*cc];
            v.x = tf32r(v.x); v.y = tf32r(v.y); v.z = tf32r(v.z); v.w = tf32r(v.w);
            *(float4*)&Ws[w*4352 + rr*68 + 4*cc] = v;
        }
        __syncthreads();

        #pragma unroll
        for (int ks = 0; ks < 8; ks++) {
            const int k = ks * 8;
            uint32_t a[2][4];
            #pragma unroll
            for (int mf = 0; mf < 2; mf++) {
                const int m = mw*32 + mf*16;
                a[mf][0] = __float_as_uint(Xs[(m + r    )*68 + k + c    ]);
                a[mf][1] = __float_as_uint(Xs[(m + r + 8)*68 + k + c    ]);
                a[mf][2] = __float_as_uint(Xs[(m + r    )*68 + k + c + 4]);
                a[mf][3] = __float_as_uint(Xs[(m + r + 8)*68 + k + c + 4]);
            }
            #pragma unroll
            for (int w = 0; w < 3; w++) {
                uint32_t b[4][2];
                #pragma unroll
                for (int nf = 0; nf < 4; nf++) {
                    const int n = nw*32 + nf*8;
                    b[nf][0] = __float_as_uint(Ws[w*4352 + (k + c    )*68 + n + r]);
                    b[nf][1] = __float_as_uint(Ws[w*4352 + (k + c + 4)*68 + n + r]);
                }
                #pragma unroll
                for (int mf = 0; mf < 2; mf++)
                    #pragma unroll
                    for (int nf = 0; nf < 4; nf++)
                        mma_tf32(acc[w][mf][nf], a[mf], b[nf]);
            }
        }
    }

    #pragma unroll
    for (int w = 0; w < 3; w++) {
        float* Out = (w == 0) ? g_Q : (w == 1) ? g_K : g_V;
        const float sc = (w == 0) ? QSCALE : 1.f;
        #pragma unroll
        for (int mf = 0; mf < 2; mf++) {
            const int mrow = m0 + mw*32 + mf*16 + r;
            #pragma unroll
            for (int nf = 0; nf < 4; nf++) {
                const int n = nw*32 + nf*8 + 2*c;
                *(float2*)&Out[(size_t)mrow * HEAD + n] =
                    make_float2(tf32r(acc[w][mf][nf][0] * sc),
                                tf32r(acc[w][mf][nf][1] * sc));
                *(float2*)&Out[(size_t)(mrow + 8) * HEAD + n] =
                    make_float2(tf32r(acc[w][mf][nf][2] * sc),
                                tf32r(acc[w][mf][nf][3] * sc));
            }
        }
    }
}

// ---------------------------------------------------------------------------
// Kernel 2: flash attention, warp-autonomous softmax (split-KV per warp).
// q-tile 64, kv-tile 256, pairs {p,31-p} -> 9 tiles/CTA, grid (16,8), 256 thr.
// Warps: mw = wid>>1 (16 q-rows), nw = wid&1 (private 128-key half).
// Each warp: own (m,l,O) over its keys, full 64 head cols; P stays in
// registers (shuffle transpose C-frag -> A-frag); combine halves at the end.
// smem (floats): Qs 64x68 | Ks 256x68 (combine buffer aliases Ks) | Vs 256x68
// = 4352 + 17408 + 17408 = 39168 floats = 156672 B
// ---------------------------------------------------------------------------
#define ATTN_SMEM_BYTES (39168 * 4)

__global__ __launch_bounds__(256, 1) void attn_mma(float* __restrict__ out)
{
    extern __shared__ float sm[];
    float* Qs = sm;                  // pitch 68
    float* Ks = sm + 4352;           // pitch 68, 256 rows
    float* Vs = sm + 21760;          // pitch 68, 256 rows
    float* Cb = Ks;                  // combine buffer (after tile loop)

    const int tid  = threadIdx.x;
    const int wid  = tid >> 5;
    const int lane = tid & 31;
    const int mw   = wid >> 1;        // 0..3 (16 q-rows)
    const int nw   = wid & 1;         // 0..1 (private 128-key half)
    const int r    = lane >> 2;
    const int c    = lane & 3;
    const int b    = blockIdx.y;

    // shuffle-transpose lane indices (C-frag cols {2c,2c+1} -> A cols {c,c+4})
    const int lane4 = lane & ~3;
    const int i1 = lane4 + (c >> 1);
    const int i2 = i1 + 2;
    const bool hi = (c & 1);

    const float* Qg = g_Q + (size_t)b * SEQ * HEAD;
    const float* Kg = g_K + (size_t)b * SEQ * HEAD;
    const float* Vg = g_V + (size_t)b * SEQ * HEAD;

    #pragma unroll 1
    for (int half = 0; half < 2; half++) {
        const int qb = half ? (31 - (int)blockIdx.x) : (int)blockIdx.x;
        const int q0 = qb * 64;
        const int ntiles = q0 / 256 + 1;

        // stage Q (pre-scaled + tf32 at producer)
        #pragma unroll
        for (int it = 0; it < 4; it++) {
            int f = tid + it * 256, cc = f & 15, rr = f >> 4;
            CP_ASYNC16(s32(&Qs[rr*68 + 4*cc]),
                       &Qg[(size_t)(q0 + rr) * HEAD + 4*cc]);
        }
        CP_COMMIT();

        float m_st[2] = { -1e29f, -1e29f };
        float l_st[2] = { 0.f, 0.f };
        float o[8][4];
        #pragma unroll
        for (int nf = 0; nf < 8; nf++)
            #pragma unroll
            for (int e = 0; e < 4; e++) o[nf][e] = 0.f;

        for (int kt = 0; kt < ntiles; kt++) {
            const int k0 = kt * 256;

            // stage K,V (256x64 each; 16+16 f4 per thread)
            #pragma unroll
            for (int it = 0; it < 16; it++) {
                int f = tid + it * 256, cc = f & 15, rr = f >> 4;
                CP_ASYNC16(s32(&Ks[rr*68 + 4*cc]),
                           &Kg[(size_t)(k0 + rr) * HEAD + 4*cc]);
                CP_ASYNC16(s32(&Vs[rr*68 + 4*cc]),
                           &Vg[(size_t)(k0 + rr) * HEAD + 4*cc]);
            }
            CP_COMMIT();
            CP_WAIT0();
            __syncthreads();   // K(kt), V(kt) (and Q) visible

            // ----- S = Q K^T : warp tile 16q x 128keys (private half) -----
            float s[16][4];
            #pragma unroll
            for (int nf = 0; nf < 16; nf++)
                #pragma unroll
                for (int e = 0; e < 4; e++) s[nf][e] = 0.f;

            #pragma unroll
            for (int ks = 0; ks < 8; ks++) {
                const int k = ks * 8;
                uint32_t a[4];
                a[0] = __float_as_uint(Qs[(mw*16 + r    )*68 + k + c    ]);
                a[1] = __float_as_uint(Qs[(mw*16 + r + 8)*68 + k + c    ]);
                a[2] = __float_as_uint(Qs[(mw*16 + r    )*68 + k + c + 4]);
                a[3] = __float_as_uint(Qs[(mw*16 + r + 8)*68 + k + c + 4]);
                #pragma unroll
                for (int nf = 0; nf < 16; nf++) {
                    const int n = nw*128 + nf*8;
                    uint32_t bb[2];
                    bb[0] = __float_as_uint(Ks[(n + r)*68 + k + c    ]);
                    bb[1] = __float_as_uint(Ks[(n + r)*68 + k + c + 4]);
                    mma_tf32(s[nf], a, bb);
                }
            }

            // ----- causal mask -----
            const int row0 = q0 + mw*16 + r;
            const int row1 = row0 + 8;
            if (k0 + 255 > q0) {
                #pragma unroll
                for (int nf = 0; nf < 16; nf++) {
                    const int col = k0 + nw*128 + nf*8 + 2*c;
                    if (col     > row0) s[nf][0] = -1e30f;
                    if (col + 1 > row0) s[nf][1] = -1e30f;
                    if (col     > row1) s[nf][2] = -1e30f;
                    if (col + 1 > row1) s[nf][3] = -1e30f;
                }
            }

            // ----- warp-local softmax (no cross-warp sync) -----
            float pm0 = s[0][0], pm1 = s[0][2];
            #pragma unroll
            for (int nf = 0; nf < 16; nf++) {
                pm0 = fmaxf(pm0, fmaxf(s[nf][0], s[nf][1]));
                pm1 = fmaxf(pm1, fmaxf(s[nf][2], s[nf][3]));
            }
            #pragma unroll
            for (int off = 1; off <= 2; off <<= 1) {
                pm0 = fmaxf(pm0, __shfl_xor_sync(0xffffffffu, pm0, off));
                pm1 = fmaxf(pm1, __shfl_xor_sync(0xffffffffu, pm1, off));
            }
            float mn0 = fmaxf(m_st[0], pm0);
            float mn1 = fmaxf(m_st[1], pm1);
            float corr0 = exp2f(m_st[0] - mn0);
            float corr1 = exp2f(m_st[1] - mn1);
            m_st[0] = mn0; m_st[1] = mn1;

            float rs0 = 0.f, rs1 = 0.f;
            #pragma unroll
            for (int nf = 0; nf < 16; nf++) {
                float p0 = exp2f(s[nf][0] - mn0);
                float p1 = exp2f(s[nf][1] - mn0);
                float p2 = exp2f(s[nf][2] - mn1);
                float p3 = exp2f(s[nf][3] - mn1);
                rs0 += p0 + p1;
                rs1 += p2 + p3;
                s[nf][0] = tf32r(p0); s[nf][1] = tf32r(p1);
                s[nf][2] = tf32r(p2); s[nf][3] = tf32r(p3);
            }
            #pragma unroll
            for (int off = 1; off <= 2; off <<= 1) {
                rs0 += __shfl_xor_sync(0xffffffffu, rs0, off);
                rs1 += __shfl_xor_sync(0xffffffffu, rs1, off);
            }
            l_st[0] = l_st[0] * corr0 + rs0;
            l_st[1] = l_st[1] * corr1 + rs1;

            #pragma unroll
            for (int nf = 0; nf < 8; nf++) {
                o[nf][0] *= corr0; o[nf][1] *= corr0;
                o[nf][2] *= corr1; o[nf][3] *= corr1;
            }

            // ----- O += P V : P via register shuffle transpose -----
            #pragma unroll
            for (int ks = 0; ks < 16; ks++) {
                // C-frag cols {2c,2c+1} -> A-frag cols {c, c+4}
                float u00 = __shfl_sync(0xffffffffu, s[ks][0], i1);
                float u01 = __shfl_sync(0xffffffffu, s[ks][1], i1);
                float u10 = __shfl_sync(0xffffffffu, s[ks][2], i1);
                float u11 = __shfl_sync(0xffffffffu, s[ks][3], i1);
                float v00 = __shfl_sync(0xffffffffu, s[ks][0], i2);
                float v01 = __shfl_sync(0xffffffffu, s[ks][1], i2);
                float v10 = __shfl_sync(0xffffffffu, s[ks][2], i2);
                float v11 = __shfl_sync(0xffffffffu, s[ks][3], i2);
                uint32_t a[4];
                a[0] = __float_as_uint(hi ? u01 : u00);   // P[row0][k+c]
                a[1] = __float_as_uint(hi ? u11 : u10);   // P[row1][k+c]
                a[2] = __float_as_uint(hi ? v01 : v00);   // P[row0][k+c+4]
                a[3] = __float_as_uint(hi ? v11 : v10);   // P[row1][k+c+4]

                const int kk = nw*128 + ks*8;
                #pragma unroll
                for (int nf = 0; nf < 8; nf++) {
                    const int n = nf*8;
                    uint32_t bb[2];
                    bb[0] = __float_as_uint(Vs[(kk + c    )*68 + n + r]);
                    bb[1] = __float_as_uint(Vs[(kk + c + 4)*68 + n + r]);
                    mma_tf32(o[nf], a, bb);
                }
            }

            __syncthreads();   // all warps done reading Ks/Vs
        }

        // ----- combine the two key-halves (split-KV merge) -----
        // nw=1 writes its (o, m, l) to Cb; nw=0 merges and stores output.
        if (nw == 1) {
            float* dst = &Cb[(mw*32 + lane) * 36];
            #pragma unroll
            for (int nf = 0; nf < 8; nf++) {
                dst[nf*4 + 0] = o[nf][0]; dst[nf*4 + 1] = o[nf][1];
                dst[nf*4 + 2] = o[nf][2]; dst[nf*4 + 3] = o[nf][3];
            }
            dst[32] = m_st[0]; dst[33] = m_st[1];
            dst[34] = l_st[0]; dst[35] = l_st[1];
        }
        __syncthreads();
        if (nw == 0) {
            const float* src = &Cb[(mw*32 + lane) * 36];
            float pm0 = src[32], pm1 = src[33];
            float pl0 = src[34], pl1 = src[35];
            float M0 = fmaxf(m_st[0], pm0);
            float M1 = fmaxf(m_st[1], pm1);
            float c00 = exp2f(m_st[0] - M0), c01 = exp2f(pm0 - M0);
            float c10 = exp2f(m_st[1] - M1), c11 = exp2f(pm1 - M1);
            float L0 = l_st[0] * c00 + pl0 * c01;
            float L1 = l_st[1] * c10 + pl1 * c11;
            float inv0 = 1.f / L0, inv1 = 1.f / L1;

            const int row0 = q0 + mw*16 + r;
            #pragma unroll
            for (int nf = 0; nf < 8; nf++) {
                const int n = nf*8 + 2*c;
                float o0 = (o[nf][0] * c00 + src[nf*4 + 0] * c01) * inv0;
                float o1 = (o[nf][1] * c00 + src[nf*4 + 1] * c01) * inv0;
                float o2 = (o[nf][2] * c10 + src[nf*4 + 2] * c11) * inv1;
                float o3 = (o[nf][3] * c10 + src[nf*4 + 3] * c11) * inv1;
                *(float2*)&out[((size_t)b * SEQ + row0) * HEAD + n] =
                    make_float2(o0, o1);
                *(float2*)&out[((size_t)b * SEQ + row0 + 8) * HEAD + n] =
                    make_float2(o2, o3);
            }
        }
        __syncthreads();   // Cb (=Ks) free before next half restages
    }
}

// ---------------------------------------------------------------------------
extern "C" void kernel_launch(void* const* d_in, const int* in_sizes, int n_in,
                              void* d_out, int out_size)
{
    const float* X  = (const float*)d_in[0];
    const float* Wq = (const float*)d_in[1];
    const float* Wk = (const float*)d_in[2];
    const float* Wv = (const float*)d_in[3];
    float* out = (float*)d_out;

    cudaFuncSetAttribute(qkv_mma,
                         cudaFuncAttributeMaxDynamicSharedMemorySize, QKV_SMEM_BYTES);
    cudaFuncSetAttribute(attn_mma,
                         cudaFuncAttributeMaxDynamicSharedMemorySize, ATTN_SMEM_BYTES);

    qkv_mma<<<128, 256, QKV_SMEM_BYTES>>>(X, Wq, Wk, Wv);

    dim3 g2(16, BATCH);
    attn_mma<<<g2, 256, ATTN_SMEM_BYTES>>>(out);
}